// round 11
// baseline (speedup 1.0000x reference)
#include <cuda_runtime.h>
#include <math.h>
#include <cstdint>

#define B_  8
#define T_  1024
#define D_  1024
#define H_  16
#define DH_ 64
#define M_  (B_*T_)     // 8192
#define N3_ (3*D_)      // 3072
#define HALF_D 512

// ---------------- scratch -------------------------------------------------------
__device__ __align__(1024) float g_xn[(size_t)M_*D_];
__device__ __align__(1024) float g_qkv[(size_t)M_*N3_];
__device__ __align__(1024) float g_attn[(size_t)M_*D_];
__device__ float g_sin[T_*HALF_D];      // [t][pair]
__device__ float g_cos[T_*HALF_D];
__device__ int   g_len[B_];
__device__ int   g_flag_q;              // 1 -> db qkv wrong, run fallback
__device__ int   g_flag_o;              // 1 -> db out wrong, run fallback

// ---------------- fast exp on the FMA pipe, x <= 0 (validated round 10) ---------
__device__ __forceinline__ float fexp(float x) {
    x = fmaxf(x, -87.0f);
    const float y = x * 1.4426950408889634f;         // x * log2(e)
    const float n = rintf(y);
    const float t = (y - n) * 0.6931471805599453f;   // |t| <= 0.3466
    float p = fmaf(t, 1.0f/120.0f, 1.0f/24.0f);
    p = fmaf(t, p, 1.0f/6.0f);
    p = fmaf(t, p, 0.5f);
    p = fmaf(t, p, 1.0f);
    p = fmaf(t, p, 1.0f);
    const int e = (int)n;
    return p * __int_as_float((e + 127) << 23);
}

// ---------------- layernorm (round-1 exact) -------------------------------------
__global__ void __launch_bounds__(256) ln_kernel(const float* __restrict__ x,
                                                 const float* __restrict__ gamma,
                                                 const float* __restrict__ beta) {
    __shared__ float ssum[8], ssq[8];
    const int row = blockIdx.x;
    const int tid = threadIdx.x;
    float4 v = *(const float4*)(x + (size_t)row * D_ + tid * 4);
    float s = v.x + v.y + v.z + v.w;
    float q = v.x*v.x + v.y*v.y + v.z*v.z + v.w*v.w;
    #pragma unroll
    for (int o = 16; o > 0; o >>= 1) {
        s += __shfl_down_sync(0xffffffffu, s, o);
        q += __shfl_down_sync(0xffffffffu, q, o);
    }
    if ((tid & 31) == 0) { ssum[tid >> 5] = s; ssq[tid >> 5] = q; }
    __syncthreads();
    float ts = 0.f, tq = 0.f;
    #pragma unroll
    for (int i = 0; i < 8; i++) { ts += ssum[i]; tq += ssq[i]; }
    const float mu  = ts * (1.f / 1024.f);
    const float var = tq * (1.f / 1024.f) - mu * mu;
    const float inv = rsqrtf(var + 1e-5f);
    float4 g  = *(const float4*)(gamma + tid * 4);
    float4 be = *(const float4*)(beta  + tid * 4);
    float4 out;
    out.x = (v.x - mu) * inv * g.x + be.x;
    out.y = (v.y - mu) * inv * g.y + be.y;
    out.z = (v.z - mu) * inv * g.z + be.z;
    out.w = (v.w - mu) * inv * g.w + be.w;
    *(float4*)(g_xn + (size_t)row * D_ + tid * 4) = out;
}

// ---------------- rope tables (round-1 exact) ------------------------------------
__global__ void rope_table_kernel() {
    const int idx = blockIdx.x * blockDim.x + threadIdx.x;
    if (idx >= T_ * HALF_D) return;
    const int t = idx >> 9;
    const int i = idx & (HALF_D - 1);
    const float e   = -(((float)i - 1.0f) * (1.0f / 512.0f));
    const float inv = expf(e * 11.512925464970229f);   // ln(1e5)
    float sn, cs;
    sincosf((float)t * inv, &sn, &cs);
    g_sin[idx] = sn;
    g_cos[idx] = cs;
}

// ---------------- sequence lengths (round-1 exact) --------------------------------
__global__ void len_kernel(const unsigned int* __restrict__ mask) {
    __shared__ int sc[8];
    const int b = blockIdx.x, tid = threadIdx.x;
    int c = 0;
    for (int i = tid; i < T_; i += 256) c += (mask[b * T_ + i] != 0u);
    #pragma unroll
    for (int o = 16; o > 0; o >>= 1) c += __shfl_down_sync(0xffffffffu, c, o);
    if ((tid & 31) == 0) sc[tid >> 5] = c;
    __syncthreads();
    if (tid == 0) {
        int t = 0;
        #pragma unroll
        for (int i = 0; i < 8; i++) t += sc[i];
        g_len[b] = t;
    }
}

// ---------------- double-buffered SGEMM: one sync per k-slice ---------------------
// 128x128 tile, 8x8/thread. Loop body: issue LDG (branchless wrap) -> compute
// current buffer -> store regs to other buffer -> single __syncthreads().
template<int N, bool ROPE>
__global__ void __launch_bounds__(256, 2) gemm_db(const float* __restrict__ A,
                                                  const float* __restrict__ Bm,
                                                  const float* __restrict__ bias,
                                                  float* __restrict__ C) {
    __shared__ float As[2][8][128];
    __shared__ float Bs[2][8][128];
    const int tid = threadIdx.x;
    const int bm = blockIdx.y, bn = blockIdx.x;
    const int arow = tid >> 1, acol = (tid & 1) << 2;
    const int brow = tid >> 5, bcol = (tid & 31) << 2;
    const int tx = tid & 15, ty = tid >> 4;

    const float* Ap = A + (size_t)(bm * 128 + arow) * 1024 + acol;
    const float* Bp = Bm + (size_t)brow * N + bn * 128 + bcol;

    float acc[8][8];
    #pragma unroll
    for (int i = 0; i < 8; i++)
        #pragma unroll
        for (int j = 0; j < 8; j++) acc[i][j] = 0.f;

    // prologue: fill buffer 0 with slice k=0
    {
        float4 a4 = *(const float4*)(Ap);
        float4 b4 = *(const float4*)(Bp);
        As[0][acol + 0][arow] = a4.x;
        As[0][acol + 1][arow] = a4.y;
        As[0][acol + 2][arow] = a4.z;
        As[0][acol + 3][arow] = a4.w;
        *(float4*)(&Bs[0][brow][bcol]) = b4;
    }
    __syncthreads();

    for (int k0 = 0; k0 < 1024; k0 += 8) {
        const int cur = (k0 >> 3) & 1;
        const int kn  = (k0 + 8) & 1023;        // branchless wrap, always in-bounds
        float4 a4 = *(const float4*)(Ap + kn);
        float4 b4 = *(const float4*)(Bp + (size_t)kn * N);

        #pragma unroll
        for (int kk = 0; kk < 8; kk++) {
            float4 a0 = *(const float4*)(&As[cur][kk][ty * 8]);
            float4 a1 = *(const float4*)(&As[cur][kk][ty * 8 + 4]);
            float4 b0 = *(const float4*)(&Bs[cur][kk][tx * 8]);
            float4 b1 = *(const float4*)(&Bs[cur][kk][tx * 8 + 4]);
            float ar[8] = {a0.x, a0.y, a0.z, a0.w, a1.x, a1.y, a1.z, a1.w};
            float br[8] = {b0.x, b0.y, b0.z, b0.w, b1.x, b1.y, b1.z, b1.w};
            #pragma unroll
            for (int i = 0; i < 8; i++)
                #pragma unroll
                for (int j = 0; j < 8; j++)
                    acc[i][j] = fmaf(ar[i], br[j], acc[i][j]);
        }

        const int nxt = cur ^ 1;
        As[nxt][acol + 0][arow] = a4.x;
        As[nxt][acol + 1][arow] = a4.y;
        As[nxt][acol + 2][arow] = a4.z;
        As[nxt][acol + 3][arow] = a4.w;
        *(float4*)(&Bs[nxt][brow][bcol]) = b4;
        __syncthreads();
    }

    const int row0 = bm * 128 + ty * 8;
    const int col0 = bn * 128 + tx * 8;
    #pragma unroll
    for (int i = 0; i < 8; i++) {
        const int r = row0 + i;
        if (ROPE) {
            const int t = r & (T_ - 1);
            #pragma unroll
            for (int j = 0; j < 8; j += 2) {
                const int c  = col0 + j;
                const int pi = (c & (D_ - 1)) >> 1;
                const float sn = g_sin[t * HALF_D + pi];
                const float cs = g_cos[t * HALF_D + pi];
                const float e = acc[i][j]     + bias[c];
                const float o = acc[i][j + 1] + bias[c + 1];
                acc[i][j]     = fmaf(e, cs, -o * sn);
                acc[i][j + 1] = fmaf(o, cs,  e * sn);
            }
        } else {
            #pragma unroll
            for (int j = 0; j < 8; j++) acc[i][j] += bias[col0 + j];
        }
        float4* out = (float4*)(C + (size_t)r * N + col0);
        out[0] = make_float4(acc[i][0], acc[i][1], acc[i][2], acc[i][3]);
        out[1] = make_float4(acc[i][4], acc[i][5], acc[i][6], acc[i][7]);
    }
}

// ---------------- round-1 SGEMM body (trusted fallback) ---------------------------
template<int N, bool ROPE>
__device__ __forceinline__ void gemm_body(const float* __restrict__ A,
                                          const float* __restrict__ Bm,
                                          const float* __restrict__ bias,
                                          float* __restrict__ C) {
    __shared__ float As[8][128];
    __shared__ float Bs[8][128];
    const int tid = threadIdx.x;
    const int bm = blockIdx.y, bn = blockIdx.x;
    const int arow = tid >> 1, acol = (tid & 1) << 2;
    const int brow = tid >> 5, bcol = (tid & 31) << 2;
    const int tx = tid & 15, ty = tid >> 4;

    const float* Ap = A + (size_t)(bm * 128 + arow) * 1024 + acol;
    const float* Bp = Bm + (size_t)brow * N + bn * 128 + bcol;

    float acc[8][8];
    #pragma unroll
    for (int i = 0; i < 8; i++)
        #pragma unroll
        for (int j = 0; j < 8; j++) acc[i][j] = 0.f;

    for (int k0 = 0; k0 < 1024; k0 += 8) {
        float4 a4 = *(const float4*)(Ap + k0);
        float4 b4 = *(const float4*)(Bp + (size_t)k0 * N);
        As[acol + 0][arow] = a4.x;
        As[acol + 1][arow] = a4.y;
        As[acol + 2][arow] = a4.z;
        As[acol + 3][arow] = a4.w;
        *(float4*)(&Bs[brow][bcol]) = b4;
        __syncthreads();
        #pragma unroll
        for (int kk = 0; kk < 8; kk++) {
            float4 a0 = *(const float4*)(&As[kk][ty * 8]);
            float4 a1 = *(const float4*)(&As[kk][ty * 8 + 4]);
            float4 b0 = *(const float4*)(&Bs[kk][tx * 8]);
            float4 b1 = *(const float4*)(&Bs[kk][tx * 8 + 4]);
            float ar[8] = {a0.x, a0.y, a0.z, a0.w, a1.x, a1.y, a1.z, a1.w};
            float br[8] = {b0.x, b0.y, b0.z, b0.w, b1.x, b1.y, b1.z, b1.w};
            #pragma unroll
            for (int i = 0; i < 8; i++)
                #pragma unroll
                for (int j = 0; j < 8; j++)
                    acc[i][j] = fmaf(ar[i], br[j], acc[i][j]);
        }
        __syncthreads();
    }

    const int row0 = bm * 128 + ty * 8;
    const int col0 = bn * 128 + tx * 8;
    #pragma unroll
    for (int i = 0; i < 8; i++) {
        const int r = row0 + i;
        if (ROPE) {
            const int t = r & (T_ - 1);
            #pragma unroll
            for (int j = 0; j < 8; j += 2) {
                const int c  = col0 + j;
                const int pi = (c & (D_ - 1)) >> 1;
                const float sn = g_sin[t * HALF_D + pi];
                const float cs = g_cos[t * HALF_D + pi];
                const float e = acc[i][j]     + bias[c];
                const float o = acc[i][j + 1] + bias[c + 1];
                acc[i][j]     = fmaf(e, cs, -o * sn);
                acc[i][j + 1] = fmaf(o, cs,  e * sn);
            }
        } else {
            #pragma unroll
            for (int j = 0; j < 8; j++) acc[i][j] += bias[col0 + j];
        }
        float4* out = (float4*)(C + (size_t)r * N + col0);
        out[0] = make_float4(acc[i][0], acc[i][1], acc[i][2], acc[i][3]);
        out[1] = make_float4(acc[i][4], acc[i][5], acc[i][6], acc[i][7]);
    }
}

__global__ void __launch_bounds__(256) gemm_fb_qkv(const float* __restrict__ W,
                                                   const float* __restrict__ b) {
    if (g_flag_q == 0) return;
    gemm_body<N3_, true>(g_xn, W, b, g_qkv);
}
__global__ void __launch_bounds__(256) gemm_fb_out(const float* __restrict__ W,
                                                   const float* __restrict__ b,
                                                   float* __restrict__ out) {
    if (g_flag_o == 0) return;
    gemm_body<D_, false>(g_attn, W, b, out);
}

// ---------------- checks (coalesced, cheap) ----------------------------------------
__global__ void __launch_bounds__(256) check_qkv_kernel(
    const float* __restrict__ W, const float* __restrict__ bias) {
    __shared__ int bad;
    const int tid = threadIdx.x, lane = tid & 31, w = tid >> 5;
    if (tid == 0) bad = 0;
    __syncthreads();
    const int row = (w * 1237 + 11) & (M_ - 1);
    const int c0  = ((w * 677) % (N3_ / 64)) * 64;
    const int ce  = c0 + lane * 2;
    const float* xr = g_xn + (size_t)row * D_;
    float se = 0.f, so = 0.f;
    for (int k = 0; k < D_; k++) {
        const float xv = xr[k];
        se = fmaf(xv, W[(size_t)k * N3_ + ce],     se);
        so = fmaf(xv, W[(size_t)k * N3_ + ce + 1], so);
    }
    se += bias[ce]; so += bias[ce + 1];
    const int t  = row & (T_ - 1);
    const int pi = (ce & (D_ - 1)) >> 1;
    const float sn = g_sin[t * HALF_D + pi], cs = g_cos[t * HALF_D + pi];
    const float re = se * cs - so * sn;
    const float ro = so * cs + se * sn;
    const float ge = g_qkv[(size_t)row * N3_ + ce];
    const float go = g_qkv[(size_t)row * N3_ + ce + 1];
    if (fabsf(ge - re) > 0.01f + 0.003f * fabsf(re) ||
        fabsf(go - ro) > 0.01f + 0.003f * fabsf(ro)) bad = 1;
    __syncthreads();
    if (tid == 0) g_flag_q = bad;
}

__global__ void __launch_bounds__(256) check_out_kernel(
    const float* __restrict__ W, const float* __restrict__ bias,
    const float* __restrict__ out) {
    __shared__ int bad;
    const int tid = threadIdx.x, lane = tid & 31, w = tid >> 5;
    if (tid == 0) bad = 0;
    __syncthreads();
    const int row = (w * 1237 + 17) & (M_ - 1);
    const int c0  = ((w * 677) % (D_ / 64)) * 64;
    const int ce  = c0 + lane * 2;
    const float* ar = g_attn + (size_t)row * D_;
    float se = 0.f, so = 0.f;
    for (int k = 0; k < D_; k++) {
        const float av = ar[k];
        se = fmaf(av, W[(size_t)k * D_ + ce],     se);
        so = fmaf(av, W[(size_t)k * D_ + ce + 1], so);
    }
    se += bias[ce]; so += bias[ce + 1];
    const float ge = out[(size_t)row * D_ + ce];
    const float go = out[(size_t)row * D_ + ce + 1];
    if (fabsf(ge - se) > 0.01f + 0.003f * fabsf(se) ||
        fabsf(go - so) > 0.01f + 0.003f * fabsf(so)) bad = 1;
    __syncthreads();
    if (tid == 0) g_flag_o = bad;
}

// ---------------- flash attention, poly-exp (validated round 10) ------------------
__global__ void __launch_bounds__(256, 1) attn_kernel() {
    __shared__ float ks[32][64];
    __shared__ float vs[32][64];
    __shared__ float scr[32][256];

    const int bh = blockIdx.y;
    const int b = bh >> 4, h = bh & 15;
    const int tid = threadIdx.x;
    const int t = blockIdx.x * 256 + tid;
    const int len = g_len[b];

    const float* qrow = g_qkv + (size_t)(b * T_ + t) * N3_ + h * DH_;
    float q[64];
    #pragma unroll
    for (int i = 0; i < 16; i++) {
        float4 v4 = *(const float4*)(qrow + i * 4);
        q[i*4+0] = v4.x; q[i*4+1] = v4.y; q[i*4+2] = v4.z; q[i*4+3] = v4.w;
    }
    float o[64];
    #pragma unroll
    for (int d = 0; d < 64; d++) o[d] = 0.f;
    float m = -1e30f, l = 0.f;

    const float* kbase = g_qkv + (size_t)(b * T_) * N3_ + D_     + h * DH_;
    const float* vbase = g_qkv + (size_t)(b * T_) * N3_ + 2 * D_ + h * DH_;

    for (int s0 = 0; s0 < T_; s0 += 32) {
        if (s0 >= len) break;
        #pragma unroll
        for (int p = 0; p < 2; p++) {
            const int idx = tid * 2 + p;
            const int r = idx >> 4, c = (idx & 15) << 2;
            *(float4*)&ks[r][c] = *(const float4*)(kbase + (size_t)(s0 + r) * N3_ + c);
            *(float4*)&vs[r][c] = *(const float4*)(vbase + (size_t)(s0 + r) * N3_ + c);
        }
        __syncthreads();

        const int nv = min(32, len - s0);
        float tmax = -1e30f;
        for (int s = 0; s < 32; s++) {
            float acc = 0.f;
            #pragma unroll
            for (int d4 = 0; d4 < 16; d4++) {
                float4 kv = *(const float4*)&ks[s][d4 * 4];
                acc = fmaf(q[d4*4+0], kv.x, acc);
                acc = fmaf(q[d4*4+1], kv.y, acc);
                acc = fmaf(q[d4*4+2], kv.z, acc);
                acc = fmaf(q[d4*4+3], kv.w, acc);
            }
            acc *= 0.125f;
            scr[s][tid] = acc;
            if (s < nv) tmax = fmaxf(tmax, acc);
        }
        const float mnew = fmaxf(m, tmax);
        const float corr = fexp(m - mnew);
        l *= corr;
        #pragma unroll
        for (int d = 0; d < 64; d++) o[d] *= corr;
        for (int s = 0; s < nv; s++) {
            const float p = fexp(scr[s][tid] - mnew);
            l += p;
            #pragma unroll
            for (int d4 = 0; d4 < 16; d4++) {
                float4 vv = *(const float4*)&vs[s][d4 * 4];
                o[d4*4+0] = fmaf(p, vv.x, o[d4*4+0]);
                o[d4*4+1] = fmaf(p, vv.y, o[d4*4+1]);
                o[d4*4+2] = fmaf(p, vv.z, o[d4*4+2]);
                o[d4*4+3] = fmaf(p, vv.w, o[d4*4+3]);
            }
        }
        m = mnew;
        __syncthreads();
    }

    const float invl = 1.f / l;
    float* of = g_attn + (size_t)(b * T_ + t) * D_ + h * DH_;
    #pragma unroll
    for (int i = 0; i < 16; i++)
        *(float4*)(of + i * 4) = make_float4(o[i*4+0]*invl, o[i*4+1]*invl,
                                             o[i*4+2]*invl, o[i*4+3]*invl);
}

// ---------------- launch -----------------------------------------------------------
extern "C" void kernel_launch(void* const* d_in, const int* in_sizes, int n_in,
                              void* d_out, int out_size) {
    const float*        x     = (const float*)d_in[0];
    const unsigned int* mask  = (const unsigned int*)d_in[1];
    const float*        gamma = (const float*)d_in[2];
    const float*        beta  = (const float*)d_in[3];
    const float*        Wqkv  = (const float*)d_in[4];
    const float*        bqkv  = (const float*)d_in[5];
    const float*        Wout  = (const float*)d_in[6];
    const float*        bout  = (const float*)d_in[7];
    float* out = (float*)d_out;

    ln_kernel<<<M_, 256>>>(x, gamma, beta);
    rope_table_kernel<<<(T_ * HALF_D + 255) / 256, 256>>>();
    len_kernel<<<B_, 256>>>(mask);

    // QKV: double-buffered attempt -> check -> flag-gated round-1 fallback
    gemm_db<N3_, true><<<dim3(N3_/128, M_/128), 256>>>(g_xn, Wqkv, bqkv, g_qkv);
    check_qkv_kernel<<<1, 256>>>(Wqkv, bqkv);
    gemm_fb_qkv<<<dim3(N3_/128, M_/128), 256>>>(Wqkv, bqkv);

    // attention: poly-exp (validated), no check
    attn_kernel<<<dim3(T_/256, B_*H_), 256>>>();

    // out-proj: double-buffered attempt -> check -> flag-gated round-1 fallback
    gemm_db<D_, false><<<dim3(D_/128, M_/128), 256>>>(g_attn, Wout, bout, out);
    check_out_kernel<<<1, 256>>>(Wout, bout, out);
    gemm_fb_out<<<dim3(D_/128, M_/128), 256>>>(Wout, bout, out);
}

// round 12
// speedup vs baseline: 1.1429x; 1.1429x over previous
#include <cuda_runtime.h>
#include <math.h>
#include <cstdint>

#define B_  8
#define T_  1024
#define D_  1024
#define H_  16
#define DH_ 64
#define M_  (B_*T_)     // 8192
#define N3_ (3*D_)      // 3072
#define HALF_D 512

// ---------------- scratch -------------------------------------------------------
__device__ __align__(1024) float g_xn[(size_t)M_*D_];
__device__ __align__(1024) float g_qkv[(size_t)M_*N3_];
__device__ __align__(1024) float g_attn[(size_t)M_*D_];
__device__ float g_sin[T_*HALF_D];      // [t][pair]
__device__ float g_cos[T_*HALF_D];
__device__ int   g_len[B_];
__device__ int   g_flag_q;              // 1 -> db qkv wrong, run fallback
__device__ int   g_flag_o;              // 1 -> db out wrong, run fallback

// ---------------- fast exp on the FMA pipe, x <= 0 (validated round 10) ---------
__device__ __forceinline__ float fexp(float x) {
    x = fmaxf(x, -87.0f);
    const float y = x * 1.4426950408889634f;         // x * log2(e)
    const float n = rintf(y);
    const float t = (y - n) * 0.6931471805599453f;   // |t| <= 0.3466
    float p = fmaf(t, 1.0f/120.0f, 1.0f/24.0f);
    p = fmaf(t, p, 1.0f/6.0f);
    p = fmaf(t, p, 0.5f);
    p = fmaf(t, p, 1.0f);
    p = fmaf(t, p, 1.0f);
    const int e = (int)n;
    return p * __int_as_float((e + 127) << 23);
}

// ---------------- layernorm (round-1 exact) -------------------------------------
__global__ void __launch_bounds__(256) ln_kernel(const float* __restrict__ x,
                                                 const float* __restrict__ gamma,
                                                 const float* __restrict__ beta) {
    __shared__ float ssum[8], ssq[8];
    const int row = blockIdx.x;
    const int tid = threadIdx.x;
    float4 v = *(const float4*)(x + (size_t)row * D_ + tid * 4);
    float s = v.x + v.y + v.z + v.w;
    float q = v.x*v.x + v.y*v.y + v.z*v.z + v.w*v.w;
    #pragma unroll
    for (int o = 16; o > 0; o >>= 1) {
        s += __shfl_down_sync(0xffffffffu, s, o);
        q += __shfl_down_sync(0xffffffffu, q, o);
    }
    if ((tid & 31) == 0) { ssum[tid >> 5] = s; ssq[tid >> 5] = q; }
    __syncthreads();
    float ts = 0.f, tq = 0.f;
    #pragma unroll
    for (int i = 0; i < 8; i++) { ts += ssum[i]; tq += ssq[i]; }
    const float mu  = ts * (1.f / 1024.f);
    const float var = tq * (1.f / 1024.f) - mu * mu;
    const float inv = rsqrtf(var + 1e-5f);
    float4 g  = *(const float4*)(gamma + tid * 4);
    float4 be = *(const float4*)(beta  + tid * 4);
    float4 out;
    out.x = (v.x - mu) * inv * g.x + be.x;
    out.y = (v.y - mu) * inv * g.y + be.y;
    out.z = (v.z - mu) * inv * g.z + be.z;
    out.w = (v.w - mu) * inv * g.w + be.w;
    *(float4*)(g_xn + (size_t)row * D_ + tid * 4) = out;
}

// ---------------- rope tables (round-1 exact) ------------------------------------
__global__ void rope_table_kernel() {
    const int idx = blockIdx.x * blockDim.x + threadIdx.x;
    if (idx >= T_ * HALF_D) return;
    const int t = idx >> 9;
    const int i = idx & (HALF_D - 1);
    const float e   = -(((float)i - 1.0f) * (1.0f / 512.0f));
    const float inv = expf(e * 11.512925464970229f);   // ln(1e5)
    float sn, cs;
    sincosf((float)t * inv, &sn, &cs);
    g_sin[idx] = sn;
    g_cos[idx] = cs;
}

// ---------------- sequence lengths (round-1 exact) --------------------------------
__global__ void len_kernel(const unsigned int* __restrict__ mask) {
    __shared__ int sc[8];
    const int b = blockIdx.x, tid = threadIdx.x;
    int c = 0;
    for (int i = tid; i < T_; i += 256) c += (mask[b * T_ + i] != 0u);
    #pragma unroll
    for (int o = 16; o > 0; o >>= 1) c += __shfl_down_sync(0xffffffffu, c, o);
    if ((tid & 31) == 0) sc[tid >> 5] = c;
    __syncthreads();
    if (tid == 0) {
        int t = 0;
        #pragma unroll
        for (int i = 0; i < 8; i++) t += sc[i];
        g_len[b] = t;
    }
}

// ---------------- double-buffered SGEMM: one sync per k-slice ---------------------
// 128x128 tile, 8x8/thread. Loop body: issue LDG (branchless wrap) -> compute
// current buffer -> store regs to other buffer -> single __syncthreads().
template<int N, bool ROPE>
__global__ void __launch_bounds__(256, 2) gemm_db(const float* __restrict__ A,
                                                  const float* __restrict__ Bm,
                                                  const float* __restrict__ bias,
                                                  float* __restrict__ C) {
    __shared__ float As[2][8][128];
    __shared__ float Bs[2][8][128];
    const int tid = threadIdx.x;
    const int bm = blockIdx.y, bn = blockIdx.x;
    const int arow = tid >> 1, acol = (tid & 1) << 2;
    const int brow = tid >> 5, bcol = (tid & 31) << 2;
    const int tx = tid & 15, ty = tid >> 4;

    const float* Ap = A + (size_t)(bm * 128 + arow) * 1024 + acol;
    const float* Bp = Bm + (size_t)brow * N + bn * 128 + bcol;

    float acc[8][8];
    #pragma unroll
    for (int i = 0; i < 8; i++)
        #pragma unroll
        for (int j = 0; j < 8; j++) acc[i][j] = 0.f;

    // prologue: fill buffer 0 with slice k=0
    {
        float4 a4 = *(const float4*)(Ap);
        float4 b4 = *(const float4*)(Bp);
        As[0][acol + 0][arow] = a4.x;
        As[0][acol + 1][arow] = a4.y;
        As[0][acol + 2][arow] = a4.z;
        As[0][acol + 3][arow] = a4.w;
        *(float4*)(&Bs[0][brow][bcol]) = b4;
    }
    __syncthreads();

    for (int k0 = 0; k0 < 1024; k0 += 8) {
        const int cur = (k0 >> 3) & 1;
        const int kn  = (k0 + 8) & 1023;        // branchless wrap, always in-bounds
        float4 a4 = *(const float4*)(Ap + kn);
        float4 b4 = *(const float4*)(Bp + (size_t)kn * N);

        #pragma unroll
        for (int kk = 0; kk < 8; kk++) {
            float4 a0 = *(const float4*)(&As[cur][kk][ty * 8]);
            float4 a1 = *(const float4*)(&As[cur][kk][ty * 8 + 4]);
            float4 b0 = *(const float4*)(&Bs[cur][kk][tx * 8]);
            float4 b1 = *(const float4*)(&Bs[cur][kk][tx * 8 + 4]);
            float ar[8] = {a0.x, a0.y, a0.z, a0.w, a1.x, a1.y, a1.z, a1.w};
            float br[8] = {b0.x, b0.y, b0.z, b0.w, b1.x, b1.y, b1.z, b1.w};
            #pragma unroll
            for (int i = 0; i < 8; i++)
                #pragma unroll
                for (int j = 0; j < 8; j++)
                    acc[i][j] = fmaf(ar[i], br[j], acc[i][j]);
        }

        const int nxt = cur ^ 1;
        As[nxt][acol + 0][arow] = a4.x;
        As[nxt][acol + 1][arow] = a4.y;
        As[nxt][acol + 2][arow] = a4.z;
        As[nxt][acol + 3][arow] = a4.w;
        *(float4*)(&Bs[nxt][brow][bcol]) = b4;
        __syncthreads();
    }

    const int row0 = bm * 128 + ty * 8;
    const int col0 = bn * 128 + tx * 8;
    #pragma unroll
    for (int i = 0; i < 8; i++) {
        const int r = row0 + i;
        if (ROPE) {
            const int t = r & (T_ - 1);
            #pragma unroll
            for (int j = 0; j < 8; j += 2) {
                const int c  = col0 + j;
                const int pi = (c & (D_ - 1)) >> 1;
                const float sn = g_sin[t * HALF_D + pi];
                const float cs = g_cos[t * HALF_D + pi];
                const float e = acc[i][j]     + bias[c];
                const float o = acc[i][j + 1] + bias[c + 1];
                acc[i][j]     = fmaf(e, cs, -o * sn);
                acc[i][j + 1] = fmaf(o, cs,  e * sn);
            }
        } else {
            #pragma unroll
            for (int j = 0; j < 8; j++) acc[i][j] += bias[col0 + j];
        }
        float4* out = (float4*)(C + (size_t)r * N + col0);
        out[0] = make_float4(acc[i][0], acc[i][1], acc[i][2], acc[i][3]);
        out[1] = make_float4(acc[i][4], acc[i][5], acc[i][6], acc[i][7]);
    }
}

// ---------------- round-1 SGEMM body (trusted fallback) ---------------------------
template<int N, bool ROPE>
__device__ __forceinline__ void gemm_body(const float* __restrict__ A,
                                          const float* __restrict__ Bm,
                                          const float* __restrict__ bias,
                                          float* __restrict__ C) {
    __shared__ float As[8][128];
    __shared__ float Bs[8][128];
    const int tid = threadIdx.x;
    const int bm = blockIdx.y, bn = blockIdx.x;
    const int arow = tid >> 1, acol = (tid & 1) << 2;
    const int brow = tid >> 5, bcol = (tid & 31) << 2;
    const int tx = tid & 15, ty = tid >> 4;

    const float* Ap = A + (size_t)(bm * 128 + arow) * 1024 + acol;
    const float* Bp = Bm + (size_t)brow * N + bn * 128 + bcol;

    float acc[8][8];
    #pragma unroll
    for (int i = 0; i < 8; i++)
        #pragma unroll
        for (int j = 0; j < 8; j++) acc[i][j] = 0.f;

    for (int k0 = 0; k0 < 1024; k0 += 8) {
        float4 a4 = *(const float4*)(Ap + k0);
        float4 b4 = *(const float4*)(Bp + (size_t)k0 * N);
        As[acol + 0][arow] = a4.x;
        As[acol + 1][arow] = a4.y;
        As[acol + 2][arow] = a4.z;
        As[acol + 3][arow] = a4.w;
        *(float4*)(&Bs[brow][bcol]) = b4;
        __syncthreads();
        #pragma unroll
        for (int kk = 0; kk < 8; kk++) {
            float4 a0 = *(const float4*)(&As[kk][ty * 8]);
            float4 a1 = *(const float4*)(&As[kk][ty * 8 + 4]);
            float4 b0 = *(const float4*)(&Bs[kk][tx * 8]);
            float4 b1 = *(const float4*)(&Bs[kk][tx * 8 + 4]);
            float ar[8] = {a0.x, a0.y, a0.z, a0.w, a1.x, a1.y, a1.z, a1.w};
            float br[8] = {b0.x, b0.y, b0.z, b0.w, b1.x, b1.y, b1.z, b1.w};
            #pragma unroll
            for (int i = 0; i < 8; i++)
                #pragma unroll
                for (int j = 0; j < 8; j++)
                    acc[i][j] = fmaf(ar[i], br[j], acc[i][j]);
        }
        __syncthreads();
    }

    const int row0 = bm * 128 + ty * 8;
    const int col0 = bn * 128 + tx * 8;
    #pragma unroll
    for (int i = 0; i < 8; i++) {
        const int r = row0 + i;
        if (ROPE) {
            const int t = r & (T_ - 1);
            #pragma unroll
            for (int j = 0; j < 8; j += 2) {
                const int c  = col0 + j;
                const int pi = (c & (D_ - 1)) >> 1;
                const float sn = g_sin[t * HALF_D + pi];
                const float cs = g_cos[t * HALF_D + pi];
                const float e = acc[i][j]     + bias[c];
                const float o = acc[i][j + 1] + bias[c + 1];
                acc[i][j]     = fmaf(e, cs, -o * sn);
                acc[i][j + 1] = fmaf(o, cs,  e * sn);
            }
        } else {
            #pragma unroll
            for (int j = 0; j < 8; j++) acc[i][j] += bias[col0 + j];
        }
        float4* out = (float4*)(C + (size_t)r * N + col0);
        out[0] = make_float4(acc[i][0], acc[i][1], acc[i][2], acc[i][3]);
        out[1] = make_float4(acc[i][4], acc[i][5], acc[i][6], acc[i][7]);
    }
}

__global__ void __launch_bounds__(256) gemm_fb_qkv(const float* __restrict__ W,
                                                   const float* __restrict__ b) {
    if (g_flag_q == 0) return;
    gemm_body<N3_, true>(g_xn, W, b, g_qkv);
}
__global__ void __launch_bounds__(256) gemm_fb_out(const float* __restrict__ W,
                                                   const float* __restrict__ b,
                                                   float* __restrict__ out) {
    if (g_flag_o == 0) return;
    gemm_body<D_, false>(g_attn, W, b, out);
}

// ---------------- checks (coalesced, cheap) ----------------------------------------
__global__ void __launch_bounds__(256) check_qkv_kernel(
    const float* __restrict__ W, const float* __restrict__ bias) {
    __shared__ int bad;
    const int tid = threadIdx.x, lane = tid & 31, w = tid >> 5;
    if (tid == 0) bad = 0;
    __syncthreads();
    const int row = (w * 1237 + 11) & (M_ - 1);
    const int c0  = ((w * 677) % (N3_ / 64)) * 64;
    const int ce  = c0 + lane * 2;
    const float* xr = g_xn + (size_t)row * D_;
    float se = 0.f, so = 0.f;
    for (int k = 0; k < D_; k++) {
        const float xv = xr[k];
        se = fmaf(xv, W[(size_t)k * N3_ + ce],     se);
        so = fmaf(xv, W[(size_t)k * N3_ + ce + 1], so);
    }
    se += bias[ce]; so += bias[ce + 1];
    const int t  = row & (T_ - 1);
    const int pi = (ce & (D_ - 1)) >> 1;
    const float sn = g_sin[t * HALF_D + pi], cs = g_cos[t * HALF_D + pi];
    const float re = se * cs - so * sn;
    const float ro = so * cs + se * sn;
    const float ge = g_qkv[(size_t)row * N3_ + ce];
    const float go = g_qkv[(size_t)row * N3_ + ce + 1];
    if (fabsf(ge - re) > 0.01f + 0.003f * fabsf(re) ||
        fabsf(go - ro) > 0.01f + 0.003f * fabsf(ro)) bad = 1;
    __syncthreads();
    if (tid == 0) g_flag_q = bad;
}

__global__ void __launch_bounds__(256) check_out_kernel(
    const float* __restrict__ W, const float* __restrict__ bias,
    const float* __restrict__ out) {
    __shared__ int bad;
    const int tid = threadIdx.x, lane = tid & 31, w = tid >> 5;
    if (tid == 0) bad = 0;
    __syncthreads();
    const int row = (w * 1237 + 17) & (M_ - 1);
    const int c0  = ((w * 677) % (D_ / 64)) * 64;
    const int ce  = c0 + lane * 2;
    const float* ar = g_attn + (size_t)row * D_;
    float se = 0.f, so = 0.f;
    for (int k = 0; k < D_; k++) {
        const float av = ar[k];
        se = fmaf(av, W[(size_t)k * D_ + ce],     se);
        so = fmaf(av, W[(size_t)k * D_ + ce + 1], so);
    }
    se += bias[ce]; so += bias[ce + 1];
    const float ge = out[(size_t)row * D_ + ce];
    const float go = out[(size_t)row * D_ + ce + 1];
    if (fabsf(ge - se) > 0.01f + 0.003f * fabsf(se) ||
        fabsf(go - so) > 0.01f + 0.003f * fabsf(so)) bad = 1;
    __syncthreads();
    if (tid == 0) g_flag_o = bad;
}

// ---------------- flash attention, poly-exp (validated round 10) ------------------
__global__ void __launch_bounds__(256, 1) attn_kernel() {
    __shared__ float ks[32][64];
    __shared__ float vs[32][64];
    __shared__ float scr[32][256];

    const int bh = blockIdx.y;
    const int b = bh >> 4, h = bh & 15;
    const int tid = threadIdx.x;
    const int t = blockIdx.x * 256 + tid;
    const int len = g_len[b];

    const float* qrow = g_qkv + (size_t)(b * T_ + t) * N3_ + h * DH_;
    float q[64];
    #pragma unroll
    for (int i = 0; i < 16; i++) {
        float4 v4 = *(const float4*)(qrow + i * 4);
        q[i*4+0] = v4.x; q[i*4+1] = v4.y; q[i*4+2] = v4.z; q[i*4+3] = v4.w;
    }
    float o[64];
    #pragma unroll
    for (int d = 0; d < 64; d++) o[d] = 0.f;
    float m = -1e30f, l = 0.f;

    const float* kbase = g_qkv + (size_t)(b * T_) * N3_ + D_     + h * DH_;
    const float* vbase = g_qkv + (size_t)(b * T_) * N3_ + 2 * D_ + h * DH_;

    for (int s0 = 0; s0 < T_; s0 += 32) {
        if (s0 >= len) break;
        #pragma unroll
        for (int p = 0; p < 2; p++) {
            const int idx = tid * 2 + p;
            const int r = idx >> 4, c = (idx & 15) << 2;
            *(float4*)&ks[r][c] = *(const float4*)(kbase + (size_t)(s0 + r) * N3_ + c);
            *(float4*)&vs[r][c] = *(const float4*)(vbase + (size_t)(s0 + r) * N3_ + c);
        }
        __syncthreads();

        const int nv = min(32, len - s0);
        float tmax = -1e30f;
        for (int s = 0; s < 32; s++) {
            float acc = 0.f;
            #pragma unroll
            for (int d4 = 0; d4 < 16; d4++) {
                float4 kv = *(const float4*)&ks[s][d4 * 4];
                acc = fmaf(q[d4*4+0], kv.x, acc);
                acc = fmaf(q[d4*4+1], kv.y, acc);
                acc = fmaf(q[d4*4+2], kv.z, acc);
                acc = fmaf(q[d4*4+3], kv.w, acc);
            }
            acc *= 0.125f;
            scr[s][tid] = acc;
            if (s < nv) tmax = fmaxf(tmax, acc);
        }
        const float mnew = fmaxf(m, tmax);
        const float corr = fexp(m - mnew);
        l *= corr;
        #pragma unroll
        for (int d = 0; d < 64; d++) o[d] *= corr;
        for (int s = 0; s < nv; s++) {
            const float p = fexp(scr[s][tid] - mnew);
            l += p;
            #pragma unroll
            for (int d4 = 0; d4 < 16; d4++) {
                float4 vv = *(const float4*)&vs[s][d4 * 4];
                o[d4*4+0] = fmaf(p, vv.x, o[d4*4+0]);
                o[d4*4+1] = fmaf(p, vv.y, o[d4*4+1]);
                o[d4*4+2] = fmaf(p, vv.z, o[d4*4+2]);
                o[d4*4+3] = fmaf(p, vv.w, o[d4*4+3]);
            }
        }
        m = mnew;
        __syncthreads();
    }

    const float invl = 1.f / l;
    float* of = g_attn + (size_t)(b * T_ + t) * D_ + h * DH_;
    #pragma unroll
    for (int i = 0; i < 16; i++)
        *(float4*)(of + i * 4) = make_float4(o[i*4+0]*invl, o[i*4+1]*invl,
                                             o[i*4+2]*invl, o[i*4+3]*invl);
}

// ---------------- launch -----------------------------------------------------------
extern "C" void kernel_launch(void* const* d_in, const int* in_sizes, int n_in,
                              void* d_out, int out_size) {
    const float*        x     = (const float*)d_in[0];
    const unsigned int* mask  = (const unsigned int*)d_in[1];
    const float*        gamma = (const float*)d_in[2];
    const float*        beta  = (const float*)d_in[3];
    const float*        Wqkv  = (const float*)d_in[4];
    const float*        bqkv  = (const float*)d_in[5];
    const float*        Wout  = (const float*)d_in[6];
    const float*        bout  = (const float*)d_in[7];
    float* out = (float*)d_out;

    ln_kernel<<<M_, 256>>>(x, gamma, beta);
    rope_table_kernel<<<(T_ * HALF_D + 255) / 256, 256>>>();
    len_kernel<<<B_, 256>>>(mask);

    // QKV: double-buffered attempt -> check -> flag-gated round-1 fallback
    gemm_db<N3_, true><<<dim3(N3_/128, M_/128), 256>>>(g_xn, Wqkv, bqkv, g_qkv);
    check_qkv_kernel<<<1, 256>>>(Wqkv, bqkv);
    gemm_fb_qkv<<<dim3(N3_/128, M_/128), 256>>>(Wqkv, bqkv);

    // attention: poly-exp (validated), no check
    attn_kernel<<<dim3(T_/256, B_*H_), 256>>>();

    // out-proj: double-buffered attempt -> check -> flag-gated round-1 fallback
    gemm_db<D_, false><<<dim3(D_/128, M_/128), 256>>>(g_attn, Wout, bout, out);
    check_out_kernel<<<1, 256>>>(Wout, bout, out);
    gemm_fb_out<<<dim3(D_/128, M_/128), 256>>>(Wout, bout, out);
}

// round 13
// speedup vs baseline: 2.6183x; 2.2908x over previous
#include <cuda_runtime.h>
#include <math.h>
#include <cstdint>

#define B_  8
#define T_  1024
#define D_  1024
#define H_  16
#define DH_ 64
#define M_  (B_*T_)     // 8192
#define N3_ (3*D_)      // 3072
#define HALF_D 512

// ---------------- scratch -------------------------------------------------------
__device__ __align__(1024) float g_xn[(size_t)M_*D_];
__device__ __align__(1024) float g_qkv[(size_t)M_*N3_];
__device__ __align__(1024) float g_attn[(size_t)M_*D_];
__device__ float g_sin[T_*HALF_D];      // [t][pair]
__device__ float g_cos[T_*HALF_D];
__device__ int   g_len[B_];
__device__ int   g_flag_a;              // 1 -> new attention wrong, run fallback

// ---------------- fast exp on the FMA pipe, x <= 0 (validated round 10) ---------
__device__ __forceinline__ float fexp(float x) {
    x = fmaxf(x, -87.0f);
    const float y = x * 1.4426950408889634f;         // x * log2(e)
    const float n = rintf(y);
    const float t = (y - n) * 0.6931471805599453f;   // |t| <= 0.3466
    float p = fmaf(t, 1.0f/120.0f, 1.0f/24.0f);
    p = fmaf(t, p, 1.0f/6.0f);
    p = fmaf(t, p, 0.5f);
    p = fmaf(t, p, 1.0f);
    p = fmaf(t, p, 1.0f);
    const int e = (int)n;
    return p * __int_as_float((e + 127) << 23);
}

// ---------------- layernorm (round-1 exact) -------------------------------------
__global__ void __launch_bounds__(256) ln_kernel(const float* __restrict__ x,
                                                 const float* __restrict__ gamma,
                                                 const float* __restrict__ beta) {
    __shared__ float ssum[8], ssq[8];
    const int row = blockIdx.x;
    const int tid = threadIdx.x;
    float4 v = *(const float4*)(x + (size_t)row * D_ + tid * 4);
    float s = v.x + v.y + v.z + v.w;
    float q = v.x*v.x + v.y*v.y + v.z*v.z + v.w*v.w;
    #pragma unroll
    for (int o = 16; o > 0; o >>= 1) {
        s += __shfl_down_sync(0xffffffffu, s, o);
        q += __shfl_down_sync(0xffffffffu, q, o);
    }
    if ((tid & 31) == 0) { ssum[tid >> 5] = s; ssq[tid >> 5] = q; }
    __syncthreads();
    float ts = 0.f, tq = 0.f;
    #pragma unroll
    for (int i = 0; i < 8; i++) { ts += ssum[i]; tq += ssq[i]; }
    const float mu  = ts * (1.f / 1024.f);
    const float var = tq * (1.f / 1024.f) - mu * mu;
    const float inv = rsqrtf(var + 1e-5f);
    float4 g  = *(const float4*)(gamma + tid * 4);
    float4 be = *(const float4*)(beta  + tid * 4);
    float4 out;
    out.x = (v.x - mu) * inv * g.x + be.x;
    out.y = (v.y - mu) * inv * g.y + be.y;
    out.z = (v.z - mu) * inv * g.z + be.z;
    out.w = (v.w - mu) * inv * g.w + be.w;
    *(float4*)(g_xn + (size_t)row * D_ + tid * 4) = out;
}

// ---------------- rope tables (round-1 exact) ------------------------------------
__global__ void rope_table_kernel() {
    const int idx = blockIdx.x * blockDim.x + threadIdx.x;
    if (idx >= T_ * HALF_D) return;
    const int t = idx >> 9;
    const int i = idx & (HALF_D - 1);
    const float e   = -(((float)i - 1.0f) * (1.0f / 512.0f));
    const float inv = expf(e * 11.512925464970229f);   // ln(1e5)
    float sn, cs;
    sincosf((float)t * inv, &sn, &cs);
    g_sin[idx] = sn;
    g_cos[idx] = cs;
}

// ---------------- sequence lengths (round-1 exact) --------------------------------
__global__ void len_kernel(const unsigned int* __restrict__ mask) {
    __shared__ int sc[8];
    const int b = blockIdx.x, tid = threadIdx.x;
    int c = 0;
    for (int i = tid; i < T_; i += 256) c += (mask[b * T_ + i] != 0u);
    #pragma unroll
    for (int o = 16; o > 0; o >>= 1) c += __shfl_down_sync(0xffffffffu, c, o);
    if ((tid & 31) == 0) sc[tid >> 5] = c;
    __syncthreads();
    if (tid == 0) {
        int t = 0;
        #pragma unroll
        for (int i = 0; i < 8; i++) t += sc[i];
        g_len[b] = t;
    }
}

// ---------------- SGEMM 128x128x8, 8x8/thread (round-1 exact, FROZEN) -------------
template<int N, bool ROPE>
__device__ __forceinline__ void gemm_body(const float* __restrict__ A,
                                          const float* __restrict__ Bm,
                                          const float* __restrict__ bias,
                                          float* __restrict__ C) {
    __shared__ float As[8][128];
    __shared__ float Bs[8][128];
    const int tid = threadIdx.x;
    const int bm = blockIdx.y, bn = blockIdx.x;
    const int arow = tid >> 1, acol = (tid & 1) << 2;
    const int brow = tid >> 5, bcol = (tid & 31) << 2;
    const int tx = tid & 15, ty = tid >> 4;

    const float* Ap = A + (size_t)(bm * 128 + arow) * 1024 + acol;
    const float* Bp = Bm + (size_t)brow * N + bn * 128 + bcol;

    float acc[8][8];
    #pragma unroll
    for (int i = 0; i < 8; i++)
        #pragma unroll
        for (int j = 0; j < 8; j++) acc[i][j] = 0.f;

    for (int k0 = 0; k0 < 1024; k0 += 8) {
        float4 a4 = *(const float4*)(Ap + k0);
        float4 b4 = *(const float4*)(Bp + (size_t)k0 * N);
        As[acol + 0][arow] = a4.x;
        As[acol + 1][arow] = a4.y;
        As[acol + 2][arow] = a4.z;
        As[acol + 3][arow] = a4.w;
        *(float4*)(&Bs[brow][bcol]) = b4;
        __syncthreads();
        #pragma unroll
        for (int kk = 0; kk < 8; kk++) {
            float4 a0 = *(const float4*)(&As[kk][ty * 8]);
            float4 a1 = *(const float4*)(&As[kk][ty * 8 + 4]);
            float4 b0 = *(const float4*)(&Bs[kk][tx * 8]);
            float4 b1 = *(const float4*)(&Bs[kk][tx * 8 + 4]);
            float ar[8] = {a0.x, a0.y, a0.z, a0.w, a1.x, a1.y, a1.z, a1.w};
            float br[8] = {b0.x, b0.y, b0.z, b0.w, b1.x, b1.y, b1.z, b1.w};
            #pragma unroll
            for (int i = 0; i < 8; i++)
                #pragma unroll
                for (int j = 0; j < 8; j++)
                    acc[i][j] = fmaf(ar[i], br[j], acc[i][j]);
        }
        __syncthreads();
    }

    const int row0 = bm * 128 + ty * 8;
    const int col0 = bn * 128 + tx * 8;
    #pragma unroll
    for (int i = 0; i < 8; i++) {
        const int r = row0 + i;
        if (ROPE) {
            const int t = r & (T_ - 1);
            #pragma unroll
            for (int j = 0; j < 8; j += 2) {
                const int c  = col0 + j;
                const int pi = (c & (D_ - 1)) >> 1;
                const float sn = g_sin[t * HALF_D + pi];
                const float cs = g_cos[t * HALF_D + pi];
                const float e = acc[i][j]     + bias[c];
                const float o = acc[i][j + 1] + bias[c + 1];
                acc[i][j]     = fmaf(e, cs, -o * sn);
                acc[i][j + 1] = fmaf(o, cs,  e * sn);
            }
        } else {
            #pragma unroll
            for (int j = 0; j < 8; j++) acc[i][j] += bias[col0 + j];
        }
        float4* out = (float4*)(C + (size_t)r * N + col0);
        out[0] = make_float4(acc[i][0], acc[i][1], acc[i][2], acc[i][3]);
        out[1] = make_float4(acc[i][4], acc[i][5], acc[i][6], acc[i][7]);
    }
}

__global__ void __launch_bounds__(256) gemm_qkv_kernel(const float* __restrict__ Wqkv,
                                                       const float* __restrict__ bqkv) {
    gemm_body<N3_, true>(g_xn, Wqkv, bqkv, g_qkv);
}
__global__ void __launch_bounds__(256) gemm_out_kernel(const float* __restrict__ Wout,
                                                       const float* __restrict__ bout,
                                                       float* __restrict__ out) {
    gemm_body<D_, false>(g_attn, Wout, bout, out);
}

// ---------------- NEW attention: 128 threads, scores in registers, 16KB smem ------
// 2 CTAs/SM (vs 1 before): no 32KB score-parking buffer, no STS/LDS round trip.
__global__ void __launch_bounds__(128) attn2_kernel() {
    __shared__ float ks[32][64];
    __shared__ float vs[32][64];

    const int bh = blockIdx.y;
    const int b = bh >> 4, h = bh & 15;
    const int tid = threadIdx.x;
    const int t = blockIdx.x * 128 + tid;
    const int len = g_len[b];

    const float* qrow = g_qkv + (size_t)(b * T_ + t) * N3_ + h * DH_;
    float q[64];
    #pragma unroll
    for (int i = 0; i < 16; i++) {
        float4 v4 = *(const float4*)(qrow + i * 4);
        q[i*4+0] = v4.x; q[i*4+1] = v4.y; q[i*4+2] = v4.z; q[i*4+3] = v4.w;
    }
    float o[64];
    #pragma unroll
    for (int d = 0; d < 64; d++) o[d] = 0.f;
    float m = -1e30f, l = 0.f;

    const float* kbase = g_qkv + (size_t)(b * T_) * N3_ + D_     + h * DH_;
    const float* vbase = g_qkv + (size_t)(b * T_) * N3_ + 2 * D_ + h * DH_;

    for (int s0 = 0; s0 < T_; s0 += 32) {
        if (s0 >= len) break;
        // cooperative K/V tile load: 512 float4 per array, 128 threads -> 4 each
        #pragma unroll
        for (int p = 0; p < 4; p++) {
            const int idx = tid + p * 128;
            const int r = idx >> 4, c = (idx & 15) << 2;
            *(float4*)&ks[r][c] = *(const float4*)(kbase + (size_t)(s0 + r) * N3_ + c);
            *(float4*)&vs[r][c] = *(const float4*)(vbase + (size_t)(s0 + r) * N3_ + c);
        }
        __syncthreads();

        const int nv = min(32, len - s0);
        float sc[32];
        float tmax = -1e30f;
        #pragma unroll
        for (int s = 0; s < 32; s++) {
            float acc = 0.f;
            #pragma unroll
            for (int d4 = 0; d4 < 16; d4++) {
                float4 kv = *(const float4*)&ks[s][d4 * 4];
                acc = fmaf(q[d4*4+0], kv.x, acc);
                acc = fmaf(q[d4*4+1], kv.y, acc);
                acc = fmaf(q[d4*4+2], kv.z, acc);
                acc = fmaf(q[d4*4+3], kv.w, acc);
            }
            acc *= 0.125f;
            sc[s] = acc;
            if (s < nv) tmax = fmaxf(tmax, acc);
        }
        const float mnew = fmaxf(m, tmax);
        const float corr = fexp(m - mnew);
        l *= corr;
        #pragma unroll
        for (int d = 0; d < 64; d++) o[d] *= corr;
        #pragma unroll
        for (int s = 0; s < 32; s++) {
            if (s < nv) {
                const float p = fexp(sc[s] - mnew);
                l += p;
                #pragma unroll
                for (int d4 = 0; d4 < 16; d4++) {
                    float4 vv = *(const float4*)&vs[s][d4 * 4];
                    o[d4*4+0] = fmaf(p, vv.x, o[d4*4+0]);
                    o[d4*4+1] = fmaf(p, vv.y, o[d4*4+1]);
                    o[d4*4+2] = fmaf(p, vv.z, o[d4*4+2]);
                    o[d4*4+3] = fmaf(p, vv.w, o[d4*4+3]);
                }
            }
        }
        m = mnew;
        __syncthreads();
    }

    const float invl = 1.f / l;
    float* of = g_attn + (size_t)(b * T_ + t) * D_ + h * DH_;
    #pragma unroll
    for (int i = 0; i < 16; i++)
        *(float4*)(of + i * 4) = make_float4(o[i*4+0]*invl, o[i*4+1]*invl,
                                             o[i*4+2]*invl, o[i*4+3]*invl);
}

// ---------------- attention check (validated round 10, expf reference) ------------
__global__ void __launch_bounds__(256) check_attn_kernel() {
    __shared__ int bad;
    const int tid = threadIdx.x, lane = tid & 31, w = tid >> 5;
    if (tid == 0) bad = 0;
    __syncthreads();
    const int b = w;
    const int h = (w * 5) & 15;
    const int t = (w * 373 + 29) & (T_ - 1);
    const int len = g_len[b];
    const float* qrow = g_qkv + (size_t)(b*T_ + t)*N3_ + h*DH_;
    float q[64];
    for (int i = 0; i < 64; i++) q[i] = qrow[i];
    float arr[32];
    const int nj = (len + 31) >> 5;
    float mmax = -1e30f;
    for (int j = 0; j < nj; j++) {
        const int s = lane + 32*j;
        float sc = -1e30f;
        if (s < len) {
            const float* kr = g_qkv + (size_t)(b*T_ + s)*N3_ + D_ + h*DH_;
            float acc = 0.f;
            for (int d = 0; d < 64; d++) acc = fmaf(q[d], kr[d], acc);
            sc = acc * 0.125f;
            mmax = fmaxf(mmax, sc);
        }
        arr[j] = sc;
    }
    #pragma unroll
    for (int o = 16; o > 0; o >>= 1)
        mmax = fmaxf(mmax, __shfl_xor_sync(0xffffffffu, mmax, o));
    float l = 0.f;
    for (int j = 0; j < nj; j++) {
        const int s = lane + 32*j;
        arr[j] = (s < len) ? expf(arr[j] - mmax) : 0.f;
        l += arr[j];
    }
    #pragma unroll
    for (int o = 16; o > 0; o >>= 1) l += __shfl_xor_sync(0xffffffffu, l, o);
    const float invl = 1.f / l;
    for (int d = 0; d < 64; d++) {
        float acc = 0.f;
        for (int j = 0; j < nj; j++) {
            const int s = lane + 32*j;
            if (s < len)
                acc = fmaf(arr[j],
                           g_qkv[(size_t)(b*T_+s)*N3_ + 2*D_ + h*DH_ + d], acc);
        }
        #pragma unroll
        for (int o = 16; o > 0; o >>= 1) acc += __shfl_xor_sync(0xffffffffu, acc, o);
        if (lane == 0) {
            const float ref = acc * invl;
            const float got = g_attn[(size_t)(b*T_+t)*D_ + h*DH_ + d];
            if (fabsf(got - ref) > 0.01f + 0.01f * fabsf(ref)) bad = 1;
        }
    }
    __syncthreads();
    if (tid == 0) g_flag_a = bad;
}

// ---------------- attention fallback (validated round-10 fexp kernel), gated ------
__global__ void __launch_bounds__(256, 1) attn_fb() {
    if (g_flag_a == 0) return;
    __shared__ float ks[32][64];
    __shared__ float vs[32][64];
    __shared__ float scr[32][256];

    const int bh = blockIdx.y;
    const int b = bh >> 4, h = bh & 15;
    const int tid = threadIdx.x;
    const int t = blockIdx.x * 256 + tid;
    const int len = g_len[b];

    const float* qrow = g_qkv + (size_t)(b * T_ + t) * N3_ + h * DH_;
    float q[64];
    #pragma unroll
    for (int i = 0; i < 16; i++) {
        float4 v4 = *(const float4*)(qrow + i * 4);
        q[i*4+0] = v4.x; q[i*4+1] = v4.y; q[i*4+2] = v4.z; q[i*4+3] = v4.w;
    }
    float o[64];
    #pragma unroll
    for (int d = 0; d < 64; d++) o[d] = 0.f;
    float m = -1e30f, l = 0.f;

    const float* kbase = g_qkv + (size_t)(b * T_) * N3_ + D_     + h * DH_;
    const float* vbase = g_qkv + (size_t)(b * T_) * N3_ + 2 * D_ + h * DH_;

    for (int s0 = 0; s0 < T_; s0 += 32) {
        if (s0 >= len) break;
        #pragma unroll
        for (int p = 0; p < 2; p++) {
            const int idx = tid * 2 + p;
            const int r = idx >> 4, c = (idx & 15) << 2;
            *(float4*)&ks[r][c] = *(const float4*)(kbase + (size_t)(s0 + r) * N3_ + c);
            *(float4*)&vs[r][c] = *(const float4*)(vbase + (size_t)(s0 + r) * N3_ + c);
        }
        __syncthreads();

        const int nv = min(32, len - s0);
        float tmax = -1e30f;
        for (int s = 0; s < 32; s++) {
            float acc = 0.f;
            #pragma unroll
            for (int d4 = 0; d4 < 16; d4++) {
                float4 kv = *(const float4*)&ks[s][d4 * 4];
                acc = fmaf(q[d4*4+0], kv.x, acc);
                acc = fmaf(q[d4*4+1], kv.y, acc);
                acc = fmaf(q[d4*4+2], kv.z, acc);
                acc = fmaf(q[d4*4+3], kv.w, acc);
            }
            acc *= 0.125f;
            scr[s][tid] = acc;
            if (s < nv) tmax = fmaxf(tmax, acc);
        }
        const float mnew = fmaxf(m, tmax);
        const float corr = fexp(m - mnew);
        l *= corr;
        #pragma unroll
        for (int d = 0; d < 64; d++) o[d] *= corr;
        for (int s = 0; s < nv; s++) {
            const float p = fexp(scr[s][tid] - mnew);
            l += p;
            #pragma unroll
            for (int d4 = 0; d4 < 16; d4++) {
                float4 vv = *(const float4*)&vs[s][d4 * 4];
                o[d4*4+0] = fmaf(p, vv.x, o[d4*4+0]);
                o[d4*4+1] = fmaf(p, vv.y, o[d4*4+1]);
                o[d4*4+2] = fmaf(p, vv.z, o[d4*4+2]);
                o[d4*4+3] = fmaf(p, vv.w, o[d4*4+3]);
            }
        }
        m = mnew;
        __syncthreads();
    }

    const float invl = 1.f / l;
    float* of = g_attn + (size_t)(b * T_ + t) * D_ + h * DH_;
    #pragma unroll
    for (int i = 0; i < 16; i++)
        *(float4*)(of + i * 4) = make_float4(o[i*4+0]*invl, o[i*4+1]*invl,
                                             o[i*4+2]*invl, o[i*4+3]*invl);
}

// ---------------- launch -----------------------------------------------------------
extern "C" void kernel_launch(void* const* d_in, const int* in_sizes, int n_in,
                              void* d_out, int out_size) {
    const float*        x     = (const float*)d_in[0];
    const unsigned int* mask  = (const unsigned int*)d_in[1];
    const float*        gamma = (const float*)d_in[2];
    const float*        beta  = (const float*)d_in[3];
    const float*        Wqkv  = (const float*)d_in[4];
    const float*        bqkv  = (const float*)d_in[5];
    const float*        Wout  = (const float*)d_in[6];
    const float*        bout  = (const float*)d_in[7];
    float* out = (float*)d_out;

    ln_kernel<<<M_, 256>>>(x, gamma, beta);
    rope_table_kernel<<<(T_ * HALF_D + 255) / 256, 256>>>();
    len_kernel<<<B_, 256>>>(mask);

    // QKV: trusted round-1 kernel (frozen)
    gemm_qkv_kernel<<<dim3(N3_/128, M_/128), 256>>>(Wqkv, bqkv);

    // attention: reg-score 128-thread kernel -> check -> gated fallback
    attn2_kernel<<<dim3(T_/128, B_*H_), 128>>>();
    check_attn_kernel<<<1, 256>>>();
    attn_fb<<<dim3(T_/256, B_*H_), 256>>>();

    // out-proj: trusted round-1 kernel (frozen)
    gemm_out_kernel<<<dim3(D_/128, M_/128), 256>>>(Wout, bout, out);
}